// round 2
// baseline (speedup 1.0000x reference)
#include <cuda_runtime.h>
#include <cuda_bf16.h>
#include <math.h>

// Problem constants
#define Bq   2
#define Tq   2048
#define Dq   1024      // D_MODEL == DI
#define DSq  16
#define Kq   4
#define ROWS (Bq*Tq)   // 4096

// ---------------- scratch (device globals; no allocation allowed) ----------
__device__ float g_xn[ROWS * Dq];        // layernorm output
__device__ float g_xz[ROWS * 2 * Dq];    // xn @ W_in
__device__ float g_xs[ROWS * Dq];        // conv + silu
__device__ float g_dt[ROWS * Dq];        // softplus(xs @ dt_w + dt_b)
__device__ float g_Bm[ROWS * DSq];
__device__ float g_Cm[ROWS * DSq];
__device__ float g_y [ROWS * Dq];        // gated scan output

// ---------------- helpers ----------------
__device__ __forceinline__ float softplusf(float v) {
    return v > 20.f ? v : log1pf(expf(v));
}
__device__ __forceinline__ float siluf(float v) {
    return v / (1.f + expf(-v));
}

// ---------------- LayerNorm: one block per row ----------------
__global__ void __launch_bounds__(256) ln_kernel(
    const float* __restrict__ x, const float* __restrict__ g,
    const float* __restrict__ b, float* __restrict__ out)
{
    int row = blockIdx.x;
    int tid = threadIdx.x;
    const float4* xr = (const float4*)(x + (long)row * Dq);
    float4 v = xr[tid];
    float s  = v.x + v.y + v.z + v.w;
    float sq = v.x*v.x + v.y*v.y + v.z*v.z + v.w*v.w;
    #pragma unroll
    for (int o = 16; o; o >>= 1) {
        s  += __shfl_xor_sync(0xffffffffu, s,  o);
        sq += __shfl_xor_sync(0xffffffffu, sq, o);
    }
    __shared__ float ss[8], ssq[8];
    if ((tid & 31) == 0) { ss[tid >> 5] = s; ssq[tid >> 5] = sq; }
    __syncthreads();
    float ts = 0.f, tq = 0.f;
    #pragma unroll
    for (int w = 0; w < 8; w++) { ts += ss[w]; tq += ssq[w]; }
    float mu  = ts * (1.f / Dq);
    float var = tq * (1.f / Dq) - mu * mu;
    float r   = rsqrtf(var + 1e-5f);
    float4 gg = ((const float4*)g)[tid];
    float4 bb = ((const float4*)b)[tid];
    float4 o4;
    o4.x = (v.x - mu) * r * gg.x + bb.x;
    o4.y = (v.y - mu) * r * gg.y + bb.y;
    o4.z = (v.z - mu) * r * gg.z + bb.z;
    o4.w = (v.w - mu) * r * gg.w + bb.w;
    ((float4*)(out + (long)row * Dq))[tid] = o4;
}

// ---------------- Tiled fp32 GEMM: C = A[MxK] * B[KxN]  (+epilogue) --------
// EPI 0: plain store
// EPI 1: softplus(v + bias[n])
// EPI 2: v + resid[m*N+n]
#define BM 128
#define BN 128
#define BKt 8
template<int EPI>
__global__ void __launch_bounds__(256) gemm_kernel(
    const float* __restrict__ A, const float* __restrict__ Bw,
    float* __restrict__ C, int M, int N, int K,
    const float* __restrict__ bias, const float* __restrict__ resid)
{
    __shared__ float As[BKt][BM];
    __shared__ float Bs[BKt][BN];
    int tid = threadIdx.x;
    int tx = tid & 15, ty = tid >> 4;           // 16x16 thread grid, 8x8 microtile
    int bm = blockIdx.y * BM, bn = blockIdx.x * BN;

    const int arow = tid >> 1;                  // 0..127
    const int acol = (tid & 1) * 4;             // 0 or 4
    const int brow = tid >> 5;                  // 0..7
    const int bcol = (tid & 31) * 4;            // 0..124

    float acc[8][8];
    #pragma unroll
    for (int i = 0; i < 8; i++)
        #pragma unroll
        for (int j = 0; j < 8; j++) acc[i][j] = 0.f;

    for (int k0 = 0; k0 < K; k0 += BKt) {
        float4 av = *(const float4*)(A + (long)(bm + arow) * K + k0 + acol);
        As[acol + 0][arow] = av.x;
        As[acol + 1][arow] = av.y;
        As[acol + 2][arow] = av.z;
        As[acol + 3][arow] = av.w;
        *(float4*)&Bs[brow][bcol] =
            *(const float4*)(Bw + (long)(k0 + brow) * N + bn + bcol);
        __syncthreads();
        #pragma unroll
        for (int kk = 0; kk < BKt; kk++) {
            float ra[8], rb[8];
            #pragma unroll
            for (int i = 0; i < 8; i++) ra[i] = As[kk][ty * 8 + i];
            #pragma unroll
            for (int j = 0; j < 8; j++) rb[j] = Bs[kk][tx * 8 + j];
            #pragma unroll
            for (int i = 0; i < 8; i++)
                #pragma unroll
                for (int j = 0; j < 8; j++) acc[i][j] += ra[i] * rb[j];
        }
        __syncthreads();
    }

    #pragma unroll
    for (int i = 0; i < 8; i++) {
        int m = bm + ty * 8 + i;
        #pragma unroll
        for (int j = 0; j < 8; j++) {
            int n = bn + tx * 8 + j;
            float v = acc[i][j];
            if (EPI == 1) v = softplusf(v + bias[n]);
            if (EPI == 2) v = v + resid[(long)m * N + n];
            C[(long)m * N + n] = v;
        }
    }
}

// ---------------- Causal depthwise conv (K=4) + SiLU -----------------------
// reads first half of g_xz, writes g_xs
__global__ void __launch_bounds__(256) conv_silu_kernel(
    const float* __restrict__ xz, const float* __restrict__ w,
    const float* __restrict__ cb, float* __restrict__ xs)
{
    int idx = blockIdx.x * blockDim.x + threadIdx.x;  // (b,t,d) flat
    int d  = idx & (Dq - 1);
    int bt = idx >> 10;
    int t  = bt & (Tq - 1);
    int b  = bt >> 11;
    float acc = cb[d];
    #pragma unroll
    for (int k = 0; k < Kq; k++) {
        int tt = t - (Kq - 1) + k;
        if (tt >= 0)
            acc += w[d * Kq + k] * xz[((long)(b * Tq + tt)) * (2 * Dq) + d];
    }
    xs[idx] = siluf(acc);
}

// ---------------- B/C projections: [4096,1024] @ [1024,16] x2 -------------
__global__ void __launch_bounds__(128) bc_kernel(
    const float* __restrict__ xs, const float* __restrict__ Bw,
    const float* __restrict__ Cw, float* __restrict__ Bm, float* __restrict__ Cm)
{
    __shared__ float xsh[Dq];
    int row = blockIdx.x;
    int tid = threadIdx.x;
    for (int i = tid; i < Dq; i += 128) xsh[i] = xs[(long)row * Dq + i];
    __syncthreads();
    int o = tid >> 2;       // 0..31 (0..15 -> B, 16..31 -> C)
    int p = tid & 3;        // partial index
    const float* W = (o < 16) ? Bw : Cw;
    int col = o & 15;
    float s = 0.f;
    int k0 = p * 256;
    for (int k = k0; k < k0 + 256; k++) s += xsh[k] * W[k * DSq + col];
    s += __shfl_xor_sync(0xffffffffu, s, 1);
    s += __shfl_xor_sync(0xffffffffu, s, 2);
    if (p == 0) {
        if (o < 16) Bm[row * DSq + col] = s;
        else        Cm[row * DSq + col] = s;
    }
}

// ---------------- Selective scan + D skip + z-gate --------------------------
// grid: Bq * (Dq/256) = 8 blocks, 256 threads; each thread owns one channel d.
__global__ void __launch_bounds__(256) scan_kernel(
    const float* __restrict__ xs, const float* __restrict__ dt,
    const float* __restrict__ Bm, const float* __restrict__ Cm,
    const float* __restrict__ log_A, const float* __restrict__ Dp,
    const float* __restrict__ xz, float* __restrict__ y)
{
    int b = blockIdx.x >> 2;
    int d = ((blockIdx.x & 3) << 8) + threadIdx.x;
    float A  = -expf(log_A[d]);
    float Dv = Dp[d];
    float h[DSq];
    #pragma unroll
    for (int s = 0; s < DSq; s++) h[s] = 0.f;

    __shared__ float Bs[64][DSq];
    __shared__ float Cs[64][DSq];

    for (int t0 = 0; t0 < Tq; t0 += 64) {
        __syncthreads();
        for (int i = threadIdx.x; i < 64 * DSq; i += 256) {
            Bs[i >> 4][i & 15] = Bm[(long)(b * Tq + t0) * DSq + i];
            Cs[i >> 4][i & 15] = Cm[(long)(b * Tq + t0) * DSq + i];
        }
        __syncthreads();
        for (int tt = 0; tt < 64; tt++) {
            long row = (long)(b * Tq + t0 + tt);
            float xv  = xs[row * Dq + d];
            float dtv = dt[row * Dq + d];
            float a = expf(fminf(dtv * A, 0.f));
            float u = dtv * xv;
            float acc = 0.f;
            #pragma unroll
            for (int s = 0; s < DSq; s++) {
                h[s] = h[s] * a + u * Bs[tt][s];
                acc += h[s] * Cs[tt][s];
            }
            float zv = xz[row * (2 * Dq) + Dq + d];
            y[row * Dq + d] = (acc + xv * Dv) * siluf(zv);
        }
    }
}

// ---------------- launch ----------------------------------------------------
extern "C" void kernel_launch(void* const* d_in, const int* in_sizes, int n_in,
                              void* d_out, int out_size)
{
    const float* x      = (const float*)d_in[0];
    const float* ln_g   = (const float*)d_in[1];
    const float* ln_b   = (const float*)d_in[2];
    const float* W_in   = (const float*)d_in[3];
    const float* conv_w = (const float*)d_in[4];
    const float* conv_b = (const float*)d_in[5];
    const float* dt_w   = (const float*)d_in[6];
    const float* dt_b   = (const float*)d_in[7];
    const float* B_w    = (const float*)d_in[8];
    const float* C_w    = (const float*)d_in[9];
    const float* log_A  = (const float*)d_in[10];
    const float* D_par  = (const float*)d_in[11];
    const float* W_out  = (const float*)d_in[12];
    float* out = (float*)d_out;

    float *xn, *xz, *xs, *dt, *Bm, *Cm, *yb;
    cudaGetSymbolAddress((void**)&xn, g_xn);
    cudaGetSymbolAddress((void**)&xz, g_xz);
    cudaGetSymbolAddress((void**)&xs, g_xs);
    cudaGetSymbolAddress((void**)&dt, g_dt);
    cudaGetSymbolAddress((void**)&Bm, g_Bm);
    cudaGetSymbolAddress((void**)&Cm, g_Cm);
    cudaGetSymbolAddress((void**)&yb, g_y);

    // 1. LayerNorm
    ln_kernel<<<ROWS, 256>>>(x, ln_g, ln_b, xn);

    // 2. xz = xn @ W_in   [4096,1024]x[1024,2048]
    gemm_kernel<0><<<dim3(2 * Dq / BN, ROWS / BM), 256>>>(
        xn, W_in, xz, ROWS, 2 * Dq, Dq, nullptr, nullptr);

    // 3. causal depthwise conv + silu
    conv_silu_kernel<<<ROWS * Dq / 256, 256>>>(xz, conv_w, conv_b, xs);

    // 4. dt = softplus(xs @ dt_w + dt_b)
    gemm_kernel<1><<<dim3(Dq / BN, ROWS / BM), 256>>>(
        xs, dt_w, dt, ROWS, Dq, Dq, dt_b, nullptr);

    // 5. Bm/Cm projections
    bc_kernel<<<ROWS, 128>>>(xs, B_w, C_w, Bm, Cm);

    // 6. selective scan + gate
    scan_kernel<<<Bq * (Dq / 256), 256>>>(xs, dt, Bm, Cm, log_A, D_par, xz, yb);

    // 7. out = residual + y @ W_out
    gemm_kernel<2><<<dim3(Dq / BN, ROWS / BM), 256>>>(
        yb, W_out, out, ROWS, Dq, Dq, nullptr, x);
}

// round 3
// speedup vs baseline: 1.9512x; 1.9512x over previous
#include <cuda_runtime.h>
#include <cuda_bf16.h>
#include <math.h>

// Problem constants
#define Bq   2
#define Tq   2048
#define Dq   1024      // D_MODEL == DI
#define DSq  16
#define Kq   4
#define ROWS (Bq*Tq)   // 4096
#define NCq  64        // scan chunks per sequence
#define Lq   (Tq/NCq)  // 32 timesteps per chunk

// ---------------- scratch (device globals; no allocation allowed) ----------
__device__ float g_xn[ROWS * Dq];        // layernorm output
__device__ float g_xz[ROWS * 2 * Dq];    // xn @ W_in
__device__ float g_xs[ROWS * Dq];        // conv + silu
__device__ float g_dt[ROWS * Dq];        // softplus(xs @ dt_w + dt_b)
__device__ float g_Bm[ROWS * DSq];
__device__ float g_Cm[ROWS * DSq];
__device__ float g_y [ROWS * Dq];        // gated scan output
__device__ float g_hend  [Bq * NCq * Dq * DSq];  // per-chunk local end state
__device__ float g_hstart[Bq * NCq * Dq * DSq];  // per-chunk true start state
__device__ float g_P     [Bq * NCq * Dq];        // per-chunk decay product

// ---------------- helpers ----------------
__device__ __forceinline__ float softplusf(float v) {
    return v > 20.f ? v : log1pf(expf(v));
}
__device__ __forceinline__ float siluf(float v) {
    return v / (1.f + expf(-v));
}

// ---------------- LayerNorm: one block per row ----------------
__global__ void __launch_bounds__(256) ln_kernel(
    const float* __restrict__ x, const float* __restrict__ g,
    const float* __restrict__ b, float* __restrict__ out)
{
    int row = blockIdx.x;
    int tid = threadIdx.x;
    const float4* xr = (const float4*)(x + (long)row * Dq);
    float4 v = xr[tid];
    float s  = v.x + v.y + v.z + v.w;
    float sq = v.x*v.x + v.y*v.y + v.z*v.z + v.w*v.w;
    #pragma unroll
    for (int o = 16; o; o >>= 1) {
        s  += __shfl_xor_sync(0xffffffffu, s,  o);
        sq += __shfl_xor_sync(0xffffffffu, sq, o);
    }
    __shared__ float ss[8], ssq[8];
    if ((tid & 31) == 0) { ss[tid >> 5] = s; ssq[tid >> 5] = sq; }
    __syncthreads();
    float ts = 0.f, tq = 0.f;
    #pragma unroll
    for (int w = 0; w < 8; w++) { ts += ss[w]; tq += ssq[w]; }
    float mu  = ts * (1.f / Dq);
    float var = tq * (1.f / Dq) - mu * mu;
    float r   = rsqrtf(var + 1e-5f);
    float4 gg = ((const float4*)g)[tid];
    float4 bb = ((const float4*)b)[tid];
    float4 o4;
    o4.x = (v.x - mu) * r * gg.x + bb.x;
    o4.y = (v.y - mu) * r * gg.y + bb.y;
    o4.z = (v.z - mu) * r * gg.z + bb.z;
    o4.w = (v.w - mu) * r * gg.w + bb.w;
    ((float4*)(out + (long)row * Dq))[tid] = o4;
}

// ---------------- Tiled fp32 GEMM: C = A[MxK] * B[KxN]  (+epilogue) --------
// EPI 0: plain store
// EPI 1: softplus(v + bias[n])
// EPI 2: v + resid[m*N+n]
#define BM 128
#define BN 128
#define BKt 8
template<int EPI>
__global__ void __launch_bounds__(256) gemm_kernel(
    const float* __restrict__ A, const float* __restrict__ Bw,
    float* __restrict__ C, int M, int N, int K,
    const float* __restrict__ bias, const float* __restrict__ resid)
{
    __shared__ float As[BKt][BM];
    __shared__ float Bs[BKt][BN];
    int tid = threadIdx.x;
    int tx = tid & 15, ty = tid >> 4;           // 16x16 thread grid, 8x8 microtile
    int bm = blockIdx.y * BM, bn = blockIdx.x * BN;

    const int arow = tid >> 1;                  // 0..127
    const int acol = (tid & 1) * 4;             // 0 or 4
    const int brow = tid >> 5;                  // 0..7
    const int bcol = (tid & 31) * 4;            // 0..124

    float acc[8][8];
    #pragma unroll
    for (int i = 0; i < 8; i++)
        #pragma unroll
        for (int j = 0; j < 8; j++) acc[i][j] = 0.f;

    for (int k0 = 0; k0 < K; k0 += BKt) {
        float4 av = *(const float4*)(A + (long)(bm + arow) * K + k0 + acol);
        As[acol + 0][arow] = av.x;
        As[acol + 1][arow] = av.y;
        As[acol + 2][arow] = av.z;
        As[acol + 3][arow] = av.w;
        *(float4*)&Bs[brow][bcol] =
            *(const float4*)(Bw + (long)(k0 + brow) * N + bn + bcol);
        __syncthreads();
        #pragma unroll
        for (int kk = 0; kk < BKt; kk++) {
            float ra[8], rb[8];
            #pragma unroll
            for (int i = 0; i < 8; i++) ra[i] = As[kk][ty * 8 + i];
            #pragma unroll
            for (int j = 0; j < 8; j++) rb[j] = Bs[kk][tx * 8 + j];
            #pragma unroll
            for (int i = 0; i < 8; i++)
                #pragma unroll
                for (int j = 0; j < 8; j++) acc[i][j] += ra[i] * rb[j];
        }
        __syncthreads();
    }

    #pragma unroll
    for (int i = 0; i < 8; i++) {
        int m = bm + ty * 8 + i;
        #pragma unroll
        for (int j = 0; j < 8; j++) {
            int n = bn + tx * 8 + j;
            float v = acc[i][j];
            if (EPI == 1) v = softplusf(v + bias[n]);
            if (EPI == 2) v = v + resid[(long)m * N + n];
            C[(long)m * N + n] = v;
        }
    }
}

// ---------------- Causal depthwise conv (K=4) + SiLU -----------------------
__global__ void __launch_bounds__(256) conv_silu_kernel(
    const float* __restrict__ xz, const float* __restrict__ w,
    const float* __restrict__ cb, float* __restrict__ xs)
{
    int idx = blockIdx.x * blockDim.x + threadIdx.x;  // (b,t,d) flat
    int d  = idx & (Dq - 1);
    int bt = idx >> 10;
    int t  = bt & (Tq - 1);
    int b  = bt >> 11;
    float acc = cb[d];
    #pragma unroll
    for (int k = 0; k < Kq; k++) {
        int tt = t - (Kq - 1) + k;
        if (tt >= 0)
            acc += w[d * Kq + k] * xz[((long)(b * Tq + tt)) * (2 * Dq) + d];
    }
    xs[idx] = siluf(acc);
}

// ---------------- B/C projections: [4096,1024] @ [1024,16] x2 -------------
__global__ void __launch_bounds__(128) bc_kernel(
    const float* __restrict__ xs, const float* __restrict__ Bw,
    const float* __restrict__ Cw, float* __restrict__ Bm, float* __restrict__ Cm)
{
    __shared__ float xsh[Dq];
    int row = blockIdx.x;
    int tid = threadIdx.x;
    for (int i = tid; i < Dq; i += 128) xsh[i] = xs[(long)row * Dq + i];
    __syncthreads();
    int o = tid >> 2;       // 0..31 (0..15 -> B, 16..31 -> C)
    int p = tid & 3;        // partial index
    const float* W = (o < 16) ? Bw : Cw;
    int col = o & 15;
    float s = 0.f;
    int k0 = p * 256;
    for (int k = k0; k < k0 + 256; k++) s += xsh[k] * W[k * DSq + col];
    s += __shfl_xor_sync(0xffffffffu, s, 1);
    s += __shfl_xor_sync(0xffffffffu, s, 2);
    if (p == 0) {
        if (o < 16) Bm[row * DSq + col] = s;
        else        Cm[row * DSq + col] = s;
    }
}

// ---------------- Chunked parallel selective scan ---------------------------
// Pass 1: per (b, chunk, d) local scan from h=0; emit end state + decay product
__global__ void __launch_bounds__(256) scan_pass1(
    const float* __restrict__ xs, const float* __restrict__ dt,
    const float* __restrict__ Bm, const float* __restrict__ log_A,
    float* __restrict__ hend, float* __restrict__ Pp)
{
    int blk = blockIdx.x;               // b*NCq*4 + c*4 + dgrp
    int b   = blk >> 8;                 // / (NCq*4)
    int rem = blk & 255;
    int c   = rem >> 2;
    int d   = ((rem & 3) << 8) + threadIdx.x;
    float A = -expf(log_A[d]);

    __shared__ float Bs[Lq][DSq];
    for (int i = threadIdx.x; i < Lq * DSq; i += 256)
        Bs[i >> 4][i & 15] = Bm[((long)(b * Tq + c * Lq)) * DSq + i];
    __syncthreads();

    float h[DSq];
    #pragma unroll
    for (int s = 0; s < DSq; s++) h[s] = 0.f;
    float slog = 0.f;

    #pragma unroll 4
    for (int tt = 0; tt < Lq; tt++) {
        long row = (long)(b * Tq + c * Lq + tt);
        float xv  = xs[row * Dq + d];
        float dtv = dt[row * Dq + d];
        float e = fminf(dtv * A, 0.f);
        slog += e;
        float a = expf(e);
        float u = dtv * xv;
        #pragma unroll
        for (int s = 0; s < DSq; s++) h[s] = h[s] * a + u * Bs[tt][s];
    }

    long base = (((long)(b * NCq + c)) * Dq + d) * DSq;
    #pragma unroll
    for (int s = 0; s < DSq; s++) hend[base + s] = h[s];
    Pp[((long)(b * NCq + c)) * Dq + d] = expf(slog);
}

// Pass 2: sequential combine over chunks, parallel over (b,d,s)
__global__ void __launch_bounds__(256) scan_pass2(
    const float* __restrict__ hend, const float* __restrict__ Pp,
    float* __restrict__ hstart)
{
    int idx = blockIdx.x * 256 + threadIdx.x;   // b*16384 + d*16 + s
    int s = idx & 15;
    int d = (idx >> 4) & (Dq - 1);
    int b = idx >> 14;
    float hs = 0.f;
    for (int c = 0; c < NCq; c++) {
        long base = (((long)(b * NCq + c)) * Dq + d) * DSq + s;
        hstart[base] = hs;
        float P = Pp[((long)(b * NCq + c)) * Dq + d];
        hs = P * hs + hend[base];
    }
}

// Pass 3: re-run each chunk from known start state; emit gated output
__global__ void __launch_bounds__(256) scan_pass3(
    const float* __restrict__ xs, const float* __restrict__ dt,
    const float* __restrict__ Bm, const float* __restrict__ Cm,
    const float* __restrict__ log_A, const float* __restrict__ Dp,
    const float* __restrict__ xz, const float* __restrict__ hstart,
    float* __restrict__ y)
{
    int blk = blockIdx.x;
    int b   = blk >> 8;
    int rem = blk & 255;
    int c   = rem >> 2;
    int d   = ((rem & 3) << 8) + threadIdx.x;
    float A  = -expf(log_A[d]);
    float Dv = Dp[d];

    __shared__ float Bs[Lq][DSq];
    __shared__ float Cs[Lq][DSq];
    for (int i = threadIdx.x; i < Lq * DSq; i += 256) {
        Bs[i >> 4][i & 15] = Bm[((long)(b * Tq + c * Lq)) * DSq + i];
        Cs[i >> 4][i & 15] = Cm[((long)(b * Tq + c * Lq)) * DSq + i];
    }
    __syncthreads();

    float h[DSq];
    long base = (((long)(b * NCq + c)) * Dq + d) * DSq;
    #pragma unroll
    for (int s = 0; s < DSq; s++) h[s] = hstart[base + s];

    #pragma unroll 4
    for (int tt = 0; tt < Lq; tt++) {
        long row = (long)(b * Tq + c * Lq + tt);
        float xv  = xs[row * Dq + d];
        float dtv = dt[row * Dq + d];
        float a = expf(fminf(dtv * A, 0.f));
        float u = dtv * xv;
        float acc = 0.f;
        #pragma unroll
        for (int s = 0; s < DSq; s++) {
            h[s] = h[s] * a + u * Bs[tt][s];
            acc += h[s] * Cs[tt][s];
        }
        float zv = xz[row * (2 * Dq) + Dq + d];
        y[row * Dq + d] = (acc + xv * Dv) * siluf(zv);
    }
}

// ---------------- launch ----------------------------------------------------
extern "C" void kernel_launch(void* const* d_in, const int* in_sizes, int n_in,
                              void* d_out, int out_size)
{
    const float* x      = (const float*)d_in[0];
    const float* ln_g   = (const float*)d_in[1];
    const float* ln_b   = (const float*)d_in[2];
    const float* W_in   = (const float*)d_in[3];
    const float* conv_w = (const float*)d_in[4];
    const float* conv_b = (const float*)d_in[5];
    const float* dt_w   = (const float*)d_in[6];
    const float* dt_b   = (const float*)d_in[7];
    const float* B_w    = (const float*)d_in[8];
    const float* C_w    = (const float*)d_in[9];
    const float* log_A  = (const float*)d_in[10];
    const float* D_par  = (const float*)d_in[11];
    const float* W_out  = (const float*)d_in[12];
    float* out = (float*)d_out;

    float *xn, *xz, *xs, *dt, *Bm, *Cm, *yb, *he, *hs, *Pp;
    cudaGetSymbolAddress((void**)&xn, g_xn);
    cudaGetSymbolAddress((void**)&xz, g_xz);
    cudaGetSymbolAddress((void**)&xs, g_xs);
    cudaGetSymbolAddress((void**)&dt, g_dt);
    cudaGetSymbolAddress((void**)&Bm, g_Bm);
    cudaGetSymbolAddress((void**)&Cm, g_Cm);
    cudaGetSymbolAddress((void**)&yb, g_y);
    cudaGetSymbolAddress((void**)&he, g_hend);
    cudaGetSymbolAddress((void**)&hs, g_hstart);
    cudaGetSymbolAddress((void**)&Pp, g_P);

    // 1. LayerNorm
    ln_kernel<<<ROWS, 256>>>(x, ln_g, ln_b, xn);

    // 2. xz = xn @ W_in   [4096,1024]x[1024,2048]
    gemm_kernel<0><<<dim3(2 * Dq / BN, ROWS / BM), 256>>>(
        xn, W_in, xz, ROWS, 2 * Dq, Dq, nullptr, nullptr);

    // 3. causal depthwise conv + silu
    conv_silu_kernel<<<ROWS * Dq / 256, 256>>>(xz, conv_w, conv_b, xs);

    // 4. dt = softplus(xs @ dt_w + dt_b)
    gemm_kernel<1><<<dim3(Dq / BN, ROWS / BM), 256>>>(
        xs, dt_w, dt, ROWS, Dq, Dq, dt_b, nullptr);

    // 5. Bm/Cm projections
    bc_kernel<<<ROWS, 128>>>(xs, B_w, C_w, Bm, Cm);

    // 6. chunked parallel selective scan + gate
    scan_pass1<<<Bq * NCq * (Dq / 256), 256>>>(xs, dt, Bm, log_A, he, Pp);
    scan_pass2<<<(Bq * Dq * DSq) / 256, 256>>>(he, Pp, hs);
    scan_pass3<<<Bq * NCq * (Dq / 256), 256>>>(xs, dt, Bm, Cm, log_A, D_par,
                                               xz, hs, yb);

    // 7. out = residual + y @ W_out
    gemm_kernel<2><<<dim3(Dq / BN, ROWS / BM), 256>>>(
        yb, W_out, out, ROWS, Dq, Dq, nullptr, x);
}

// round 6
// speedup vs baseline: 3.9373x; 2.0179x over previous
#include <cuda_runtime.h>
#include <cuda_bf16.h>
#include <math.h>
#include <stdint.h>

// Problem constants
#define Bq   2
#define Tq   2048
#define Dq   1024      // D_MODEL == DI
#define DSq  16
#define Kq   4
#define ROWS (Bq*Tq)   // 4096
#define NCq  64        // scan chunks per sequence
#define Lq   (Tq/NCq)  // 32 timesteps per chunk

// ---------------- scratch (device globals; no allocation allowed) ----------
__device__ float g_xn[ROWS * Dq];        // layernorm output
__device__ float g_xz[ROWS * 2 * Dq];    // xn @ W_in
__device__ float g_xs[ROWS * Dq];        // conv + silu
__device__ float g_dt[ROWS * Dq];        // softplus(xs @ dt_w + dt_b)
__device__ float g_Bm[ROWS * DSq];
__device__ float g_Cm[ROWS * DSq];
__device__ float g_y [ROWS * Dq];        // gated scan output
__device__ float g_hend  [Bq * NCq * Dq * DSq];
__device__ float g_hstart[Bq * NCq * Dq * DSq];
__device__ float g_P     [Bq * NCq * Dq];
// bf16 split buffers (reused between GEMMs; single stream => sequential)
__device__ __nv_bfloat16 g_ah[ROWS * Dq];      // activation hi
__device__ __nv_bfloat16 g_al[ROWS * Dq];      // activation lo
__device__ __nv_bfloat16 g_wh[2 * Dq * Dq];    // transposed weight hi [N,K]
__device__ __nv_bfloat16 g_wl[2 * Dq * Dq];    // transposed weight lo [N,K]

// ---------------- math helpers ----------------
__device__ __forceinline__ float softplusf(float v) {
    return v > 20.f ? v : log1pf(expf(v));
}
__device__ __forceinline__ float siluf(float v) {
    return v / (1.f + expf(-v));
}

// ---------------- PTX helpers (sm_80+ baseline; no 'a' features) ----------
__device__ __forceinline__ uint32_t smem_u32(const void* p) {
    uint32_t a;
    asm("{ .reg .u64 t; cvta.to.shared.u64 t, %1; cvt.u32.u64 %0, t; }"
        : "=r"(a) : "l"(p));
    return a;
}
__device__ __forceinline__ void cp16(uint32_t dst, const void* src) {
    asm volatile("cp.async.cg.shared.global [%0], [%1], 16;"
                 :: "r"(dst), "l"(src));
}
__device__ __forceinline__ void ldm_x4(uint32_t& r0, uint32_t& r1,
                                       uint32_t& r2, uint32_t& r3, uint32_t a) {
    asm volatile("ldmatrix.sync.aligned.m8n8.x4.shared.b16 {%0,%1,%2,%3}, [%4];"
                 : "=r"(r0), "=r"(r1), "=r"(r2), "=r"(r3) : "r"(a));
}
__device__ __forceinline__ void mma16816(float& c0, float& c1, float& c2, float& c3,
                                         uint32_t a0, uint32_t a1, uint32_t a2, uint32_t a3,
                                         uint32_t b0, uint32_t b1) {
    asm volatile("mma.sync.aligned.m16n8k16.row.col.f32.bf16.bf16.f32 "
                 "{%0,%1,%2,%3}, {%4,%5,%6,%7}, {%8,%9}, {%0,%1,%2,%3};"
                 : "+f"(c0), "+f"(c1), "+f"(c2), "+f"(c3)
                 : "r"(a0), "r"(a1), "r"(a2), "r"(a3), "r"(b0), "r"(b1));
}

// ---------------- fp32 -> bf16 hi/lo split (activations, row-major) --------
__global__ void __launch_bounds__(256) convert_act_kernel(
    const float* __restrict__ in, __nv_bfloat16* __restrict__ hi,
    __nv_bfloat16* __restrict__ lo, int n4)
{
    int i = blockIdx.x * 256 + threadIdx.x;
    if (i >= n4) return;
    float4 v = ((const float4*)in)[i];
    __nv_bfloat16 h0 = __float2bfloat16(v.x), h1 = __float2bfloat16(v.y);
    __nv_bfloat16 h2 = __float2bfloat16(v.z), h3 = __float2bfloat16(v.w);
    __nv_bfloat16 l0 = __float2bfloat16(v.x - __bfloat162float(h0));
    __nv_bfloat16 l1 = __float2bfloat16(v.y - __bfloat162float(h1));
    __nv_bfloat16 l2 = __float2bfloat16(v.z - __bfloat162float(h2));
    __nv_bfloat16 l3 = __float2bfloat16(v.w - __bfloat162float(h3));
    ((__nv_bfloat162*)hi)[2*i]   = __halves2bfloat162(h0, h1);
    ((__nv_bfloat162*)hi)[2*i+1] = __halves2bfloat162(h2, h3);
    ((__nv_bfloat162*)lo)[2*i]   = __halves2bfloat162(l0, l1);
    ((__nv_bfloat162*)lo)[2*i+1] = __halves2bfloat162(l2, l3);
}

// ---------------- weight [K,N] -> transposed hi/lo bf16 [N,K] --------------
__global__ void __launch_bounds__(256) convert_wt_kernel(
    const float* __restrict__ W, __nv_bfloat16* __restrict__ hiT,
    __nv_bfloat16* __restrict__ loT, int K, int N)
{
    __shared__ float sm[32][33];
    int n0 = blockIdx.x * 32, k0 = blockIdx.y * 32;
    int tx = threadIdx.x & 31, ty = threadIdx.x >> 5;
    #pragma unroll
    for (int i = 0; i < 4; i++)
        sm[ty + i * 8][tx] = W[(long)(k0 + ty + i * 8) * N + n0 + tx];
    __syncthreads();
    #pragma unroll
    for (int i = 0; i < 4; i++) {
        int n = n0 + ty + i * 8, k = k0 + tx;
        float v = sm[tx][ty + i * 8];
        __nv_bfloat16 h = __float2bfloat16(v);
        hiT[(long)n * K + k] = h;
        loT[(long)n * K + k] = __float2bfloat16(v - __bfloat162float(h));
    }
}

// ---------------- mma.sync bf16 GEMM: C[M,N] = A[M,K] * W[K,N] -------------
// A split bf16 row-major [M,K]; W split bf16 transposed [N,K] (K-contiguous).
// acc += Ah*Bh + Ah*Bl + Al*Bh (fp32 register accumulators).
// 128x128 CTA tile, BK=32, 8 warps (2m x 4n), 64x32 per warp.
// SMEM rows padded to 80B (stride 40 bf16) -> conflict-free ldmatrix.
#define BKg    32
#define SROW   40                      // bf16 elems per smem row (80 bytes)
#define TILE_B (128 * SROW * 2)        // 10240 B per tile
#define STAGE_B (4 * TILE_B)           // Ah,Al,Bh,Bl = 40960 B per stage
#define GSM_SZ  (2 * STAGE_B)          // 81920 B double buffered

__device__ __forceinline__ void stage_loads(
    uint32_t sbase, const __nv_bfloat16* __restrict__ Ah,
    const __nv_bfloat16* __restrict__ Al, const __nv_bfloat16* __restrict__ Bh,
    const __nv_bfloat16* __restrict__ Bl, int bm, int bn, int K, int k0, int tid)
{
    #pragma unroll
    for (int arr = 0; arr < 4; arr++) {
        const __nv_bfloat16* s = (arr == 0) ? Ah : (arr == 1) ? Al
                               : (arr == 2) ? Bh : Bl;
        int rb = (arr < 2) ? bm : bn;
        #pragma unroll
        for (int i = 0; i < 2; i++) {
            int idx = tid + i * 256;          // 0..511
            int row = idx >> 2, seg = idx & 3;
            cp16(sbase + arr * TILE_B + (row * SROW + seg * 8) * 2,
                 s + (long)(rb + row) * K + k0 + seg * 8);
        }
    }
    asm volatile("cp.async.commit_group;" ::: "memory");
}

template<int EPI>
__global__ void __launch_bounds__(256) gemm_mma(
    const __nv_bfloat16* __restrict__ Ah, const __nv_bfloat16* __restrict__ Al,
    const __nv_bfloat16* __restrict__ Bh, const __nv_bfloat16* __restrict__ Bl,
    float* __restrict__ C, int M, int N, int K,
    const float* __restrict__ bias, const float* __restrict__ resid)
{
    extern __shared__ char smem[];
    uint32_t sb = smem_u32(smem);
    int tid = threadIdx.x, wid = tid >> 5, lane = tid & 31;
    int bm = blockIdx.y * 128, bn = blockIdx.x * 128;
    int wm = (wid >> 2) * 64;         // warp m offset: 0 / 64
    int wn = (wid & 3) * 32;          // warp n offset: 0/32/64/96

    float acc[4][4][4];
    #pragma unroll
    for (int i = 0; i < 4; i++)
        #pragma unroll
        for (int j = 0; j < 4; j++)
            #pragma unroll
            for (int r = 0; r < 4; r++) acc[i][j][r] = 0.f;

    stage_loads(sb,           Ah, Al, Bh, Bl, bm, bn, K, 0,   tid);
    stage_loads(sb + STAGE_B, Ah, Al, Bh, Bl, bm, bn, K, BKg, tid);

    const int NK = K / BKg;           // 32
    // ldmatrix address components (within a tile)
    int a_row = lane & 15;            // + mi*16 + wm
    int a_seg = (lane >> 4) * 8;      // k half
    int b_row = (lane & 7) + ((lane >> 4) * 8);   // + nb*16 + wn
    int b_seg = ((lane >> 3) & 1) * 8;

    for (int kt = 0; kt < NK; kt++) {
        asm volatile("cp.async.wait_group 1;" ::: "memory");
        __syncthreads();
        uint32_t stg = sb + (kt & 1) * STAGE_B;
        #pragma unroll
        for (int ks = 0; ks < 2; ks++) {
            int k0 = ks * 16;
            uint32_t aH[4][4], aL[4][4];
            #pragma unroll
            for (int mi = 0; mi < 4; mi++) {
                int r = wm + mi * 16 + a_row;
                uint32_t off = (r * SROW + k0 + a_seg) * 2;
                ldm_x4(aH[mi][0], aH[mi][1], aH[mi][2], aH[mi][3], stg + off);
                ldm_x4(aL[mi][0], aL[mi][1], aL[mi][2], aL[mi][3],
                       stg + TILE_B + off);
            }
            #pragma unroll
            for (int nb = 0; nb < 2; nb++) {    // two n16 halves of warp n32
                int rr = wn + nb * 16 + b_row;
                uint32_t off = (rr * SROW + k0 + b_seg) * 2;
                uint32_t bH[4], bL[4];
                ldm_x4(bH[0], bH[1], bH[2], bH[3], stg + 2 * TILE_B + off);
                ldm_x4(bL[0], bL[1], bL[2], bL[3], stg + 3 * TILE_B + off);
                #pragma unroll
                for (int mi = 0; mi < 4; mi++) {
                    #pragma unroll
                    for (int h = 0; h < 2; h++) {   // n8 frag within n16
                        int nj = nb * 2 + h;
                        float* c = acc[mi][nj];
                        mma16816(c[0], c[1], c[2], c[3],
                                 aH[mi][0], aH[mi][1], aH[mi][2], aH[mi][3],
                                 bH[2*h], bH[2*h+1]);
                        mma16816(c[0], c[1], c[2], c[3],
                                 aH[mi][0], aH[mi][1], aH[mi][2], aH[mi][3],
                                 bL[2*h], bL[2*h+1]);
                        mma16816(c[0], c[1], c[2], c[3],
                                 aL[mi][0], aL[mi][1], aL[mi][2], aL[mi][3],
                                 bH[2*h], bH[2*h+1]);
                    }
                }
            }
        }
        __syncthreads();
        if (kt + 2 < NK)
            stage_loads(sb + (kt & 1) * STAGE_B, Ah, Al, Bh, Bl,
                        bm, bn, K, (kt + 2) * BKg, tid);
        else
            asm volatile("cp.async.commit_group;" ::: "memory");
    }

    // ---- epilogue: fragment layout -> direct float2 stores
    int g  = lane >> 2;               // 0..7
    int tg = lane & 3;                // 0..3
    #pragma unroll
    for (int mi = 0; mi < 4; mi++) {
        #pragma unroll
        for (int nj = 0; nj < 4; nj++) {
            int n0 = bn + wn + nj * 8 + tg * 2;
            float* c = acc[mi][nj];
            #pragma unroll
            for (int rh = 0; rh < 2; rh++) {       // row g / g+8
                int m = bm + wm + mi * 16 + g + rh * 8;
                float v0 = c[rh * 2 + 0], v1 = c[rh * 2 + 1];
                if (EPI == 1) {
                    v0 = softplusf(v0 + bias[n0]);
                    v1 = softplusf(v1 + bias[n0 + 1]);
                }
                if (EPI == 2) {
                    const float* rp = resid + (long)m * N + n0;
                    v0 += rp[0]; v1 += rp[1];
                }
                float2 st = make_float2(v0, v1);
                *(float2*)(C + (long)m * N + n0) = st;
            }
        }
    }
}

// ---------------- LayerNorm: one block per row ----------------
__global__ void __launch_bounds__(256) ln_kernel(
    const float* __restrict__ x, const float* __restrict__ g,
    const float* __restrict__ b, float* __restrict__ out)
{
    int row = blockIdx.x;
    int tid = threadIdx.x;
    const float4* xr = (const float4*)(x + (long)row * Dq);
    float4 v = xr[tid];
    float s  = v.x + v.y + v.z + v.w;
    float sq = v.x*v.x + v.y*v.y + v.z*v.z + v.w*v.w;
    #pragma unroll
    for (int o = 16; o; o >>= 1) {
        s  += __shfl_xor_sync(0xffffffffu, s,  o);
        sq += __shfl_xor_sync(0xffffffffu, sq, o);
    }
    __shared__ float ss[8], ssq[8];
    if ((tid & 31) == 0) { ss[tid >> 5] = s; ssq[tid >> 5] = sq; }
    __syncthreads();
    float ts = 0.f, tq = 0.f;
    #pragma unroll
    for (int w = 0; w < 8; w++) { ts += ss[w]; tq += ssq[w]; }
    float mu  = ts * (1.f / Dq);
    float var = tq * (1.f / Dq) - mu * mu;
    float r   = rsqrtf(var + 1e-5f);
    float4 gg = ((const float4*)g)[tid];
    float4 bb = ((const float4*)b)[tid];
    float4 o4;
    o4.x = (v.x - mu) * r * gg.x + bb.x;
    o4.y = (v.y - mu) * r * gg.y + bb.y;
    o4.z = (v.z - mu) * r * gg.z + bb.z;
    o4.w = (v.w - mu) * r * gg.w + bb.w;
    ((float4*)(out + (long)row * Dq))[tid] = o4;
}

// ---------------- Causal depthwise conv (K=4) + SiLU -----------------------
__global__ void __launch_bounds__(256) conv_silu_kernel(
    const float* __restrict__ xz, const float* __restrict__ w,
    const float* __restrict__ cb, float* __restrict__ xs)
{
    int idx = blockIdx.x * blockDim.x + threadIdx.x;
    int d  = idx & (Dq - 1);
    int bt = idx >> 10;
    int t  = bt & (Tq - 1);
    int b  = bt >> 11;
    float acc = cb[d];
    #pragma unroll
    for (int k = 0; k < Kq; k++) {
        int tt = t - (Kq - 1) + k;
        if (tt >= 0)
            acc += w[d * Kq + k] * xz[((long)(b * Tq + tt)) * (2 * Dq) + d];
    }
    xs[idx] = siluf(acc);
}

// ---------------- B/C projections: [4096,1024] @ [1024,16] x2 -------------
__global__ void __launch_bounds__(128) bc_kernel(
    const float* __restrict__ xs, const float* __restrict__ Bw,
    const float* __restrict__ Cw, float* __restrict__ Bm, float* __restrict__ Cm)
{
    __shared__ float xsh[Dq];
    int row = blockIdx.x;
    int tid = threadIdx.x;
    for (int i = tid; i < Dq; i += 128) xsh[i] = xs[(long)row * Dq + i];
    __syncthreads();
    int o = tid >> 2;
    int p = tid & 3;
    const float* W = (o < 16) ? Bw : Cw;
    int col = o & 15;
    float s = 0.f;
    int k0 = p * 256;
    for (int k = k0; k < k0 + 256; k++) s += xsh[k] * W[k * DSq + col];
    s += __shfl_xor_sync(0xffffffffu, s, 1);
    s += __shfl_xor_sync(0xffffffffu, s, 2);
    if (p == 0) {
        if (o < 16) Bm[row * DSq + col] = s;
        else        Cm[row * DSq + col] = s;
    }
}

// ---------------- Chunked parallel selective scan ---------------------------
__global__ void __launch_bounds__(256) scan_pass1(
    const float* __restrict__ xs, const float* __restrict__ dt,
    const float* __restrict__ Bm, const float* __restrict__ log_A,
    float* __restrict__ hend, float* __restrict__ Pp)
{
    int blk = blockIdx.x;
    int b   = blk >> 8;
    int rem = blk & 255;
    int c   = rem >> 2;
    int d   = ((rem & 3) << 8) + threadIdx.x;
    float A = -expf(log_A[d]);

    __shared__ float Bs[Lq][DSq];
    for (int i = threadIdx.x; i < Lq * DSq; i += 256)
        Bs[i >> 4][i & 15] = Bm[((long)(b * Tq + c * Lq)) * DSq + i];
    __syncthreads();

    float h[DSq];
    #pragma unroll
    for (int s = 0; s < DSq; s++) h[s] = 0.f;
    float slog = 0.f;

    #pragma unroll 4
    for (int tt = 0; tt < Lq; tt++) {
        long row = (long)(b * Tq + c * Lq + tt);
        float xv  = xs[row * Dq + d];
        float dtv = dt[row * Dq + d];
        float e = fminf(dtv * A, 0.f);
        slog += e;
        float a = expf(e);
        float u = dtv * xv;
        #pragma unroll
        for (int s = 0; s < DSq; s++) h[s] = h[s] * a + u * Bs[tt][s];
    }

    long base = (((long)(b * NCq + c)) * Dq + d) * DSq;
    #pragma unroll
    for (int s = 0; s < DSq; s++) hend[base + s] = h[s];
    Pp[((long)(b * NCq + c)) * Dq + d] = expf(slog);
}

__global__ void __launch_bounds__(256) scan_pass2(
    const float* __restrict__ hend, const float* __restrict__ Pp,
    float* __restrict__ hstart)
{
    int idx = blockIdx.x * 256 + threadIdx.x;
    int s = idx & 15;
    int d = (idx >> 4) & (Dq - 1);
    int b = idx >> 14;
    float hs = 0.f;
    for (int c = 0; c < NCq; c++) {
        long base = (((long)(b * NCq + c)) * Dq + d) * DSq + s;
        hstart[base] = hs;
        float P = Pp[((long)(b * NCq + c)) * Dq + d];
        hs = P * hs + hend[base];
    }
}

__global__ void __launch_bounds__(256) scan_pass3(
    const float* __restrict__ xs, const float* __restrict__ dt,
    const float* __restrict__ Bm, const float* __restrict__ Cm,
    const float* __restrict__ log_A, const float* __restrict__ Dp,
    const float* __restrict__ xz, const float* __restrict__ hstart,
    float* __restrict__ y)
{
    int blk = blockIdx.x;
    int b   = blk >> 8;
    int rem = blk & 255;
    int c   = rem >> 2;
    int d   = ((rem & 3) << 8) + threadIdx.x;
    float A  = -expf(log_A[d]);
    float Dv = Dp[d];

    __shared__ float Bs[Lq][DSq];
    __shared__ float Cs[Lq][DSq];
    for (int i = threadIdx.x; i < Lq * DSq; i += 256) {
        Bs[i >> 4][i & 15] = Bm[((long)(b * Tq + c * Lq)) * DSq + i];
        Cs[i >> 4][i & 15] = Cm[((long)(b * Tq + c * Lq)) * DSq + i];
    }
    __syncthreads();

    float h[DSq];
    long base = (((long)(b * NCq + c)) * Dq + d) * DSq;
    #pragma unroll
    for (int s = 0; s < DSq; s++) h[s] = hstart[base + s];

    #pragma unroll 4
    for (int tt = 0; tt < Lq; tt++) {
        long row = (long)(b * Tq + c * Lq + tt);
        float xv  = xs[row * Dq + d];
        float dtv = dt[row * Dq + d];
        float a = expf(fminf(dtv * A, 0.f));
        float u = dtv * xv;
        float acc = 0.f;
        #pragma unroll
        for (int s = 0; s < DSq; s++) {
            h[s] = h[s] * a + u * Bs[tt][s];
            acc += h[s] * Cs[tt][s];
        }
        float zv = xz[row * (2 * Dq) + Dq + d];
        y[row * Dq + d] = (acc + xv * Dv) * siluf(zv);
    }
}

// ---------------- launch ----------------------------------------------------
extern "C" void kernel_launch(void* const* d_in, const int* in_sizes, int n_in,
                              void* d_out, int out_size)
{
    const float* x      = (const float*)d_in[0];
    const float* ln_g   = (const float*)d_in[1];
    const float* ln_b   = (const float*)d_in[2];
    const float* W_in   = (const float*)d_in[3];
    const float* conv_w = (const float*)d_in[4];
    const float* conv_b = (const float*)d_in[5];
    const float* dt_w   = (const float*)d_in[6];
    const float* dt_b   = (const float*)d_in[7];
    const float* B_w    = (const float*)d_in[8];
    const float* C_w    = (const float*)d_in[9];
    const float* log_A  = (const float*)d_in[10];
    const float* D_par  = (const float*)d_in[11];
    const float* W_out  = (const float*)d_in[12];
    float* out = (float*)d_out;

    float *xn, *xz, *xs, *dt, *Bm, *Cm, *yb, *he, *hs, *Pp;
    __nv_bfloat16 *ah, *al, *wh, *wl;
    cudaGetSymbolAddress((void**)&xn, g_xn);
    cudaGetSymbolAddress((void**)&xz, g_xz);
    cudaGetSymbolAddress((void**)&xs, g_xs);
    cudaGetSymbolAddress((void**)&dt, g_dt);
    cudaGetSymbolAddress((void**)&Bm, g_Bm);
    cudaGetSymbolAddress((void**)&Cm, g_Cm);
    cudaGetSymbolAddress((void**)&yb, g_y);
    cudaGetSymbolAddress((void**)&he, g_hend);
    cudaGetSymbolAddress((void**)&hs, g_hstart);
    cudaGetSymbolAddress((void**)&Pp, g_P);
    cudaGetSymbolAddress((void**)&ah, g_ah);
    cudaGetSymbolAddress((void**)&al, g_al);
    cudaGetSymbolAddress((void**)&wh, g_wh);
    cudaGetSymbolAddress((void**)&wl, g_wl);

    cudaFuncSetAttribute(gemm_mma<0>, cudaFuncAttributeMaxDynamicSharedMemorySize, GSM_SZ);
    cudaFuncSetAttribute(gemm_mma<1>, cudaFuncAttributeMaxDynamicSharedMemorySize, GSM_SZ);
    cudaFuncSetAttribute(gemm_mma<2>, cudaFuncAttributeMaxDynamicSharedMemorySize, GSM_SZ);

    // 1. LayerNorm
    ln_kernel<<<ROWS, 256>>>(x, ln_g, ln_b, xn);

    // 2. xz = xn @ W_in   [4096,1024]x[1024,2048]  (mma.sync bf16 split)
    convert_act_kernel<<<ROWS * Dq / 1024, 256>>>(xn, ah, al, ROWS * Dq / 4);
    convert_wt_kernel<<<dim3(2 * Dq / 32, Dq / 32), 256>>>(W_in, wh, wl, Dq, 2 * Dq);
    gemm_mma<0><<<dim3(2 * Dq / 128, ROWS / 128), 256, GSM_SZ>>>(
        ah, al, wh, wl, xz, ROWS, 2 * Dq, Dq, nullptr, nullptr);

    // 3. causal depthwise conv + silu
    conv_silu_kernel<<<ROWS * Dq / 256, 256>>>(xz, conv_w, conv_b, xs);

    // 4. dt = softplus(xs @ dt_w + dt_b)
    convert_act_kernel<<<ROWS * Dq / 1024, 256>>>(xs, ah, al, ROWS * Dq / 4);
    convert_wt_kernel<<<dim3(Dq / 32, Dq / 32), 256>>>(dt_w, wh, wl, Dq, Dq);
    gemm_mma<1><<<dim3(Dq / 128, ROWS / 128), 256, GSM_SZ>>>(
        ah, al, wh, wl, dt, ROWS, Dq, Dq, dt_b, nullptr);

    // 5. Bm/Cm projections
    bc_kernel<<<ROWS, 128>>>(xs, B_w, C_w, Bm, Cm);

    // 6. chunked parallel selective scan + gate
    scan_pass1<<<Bq * NCq * (Dq / 256), 256>>>(xs, dt, Bm, log_A, he, Pp);
    scan_pass2<<<(Bq * Dq * DSq) / 256, 256>>>(he, Pp, hs);
    scan_pass3<<<Bq * NCq * (Dq / 256), 256>>>(xs, dt, Bm, Cm, log_A, D_par,
                                               xz, hs, yb);

    // 7. out = residual + y @ W_out
    convert_act_kernel<<<ROWS * Dq / 1024, 256>>>(yb, ah, al, ROWS * Dq / 4);
    convert_wt_kernel<<<dim3(Dq / 32, Dq / 32), 256>>>(W_out, wh, wl, Dq, Dq);
    gemm_mma<2><<<dim3(Dq / 128, ROWS / 128), 256, GSM_SZ>>>(
        ah, al, wh, wl, out, ROWS, Dq, Dq, nullptr, x);
}